// round 1
// baseline (speedup 1.0000x reference)
#include <cuda_runtime.h>
#include <cuda_bf16.h>
#include <cstdint>
#include <math.h>

// SoftmaxSetAttention: B=2, H=16, Lq=Lk=2048, D=128, fp32 io.
// out = softmax(QK^T/sqrt(D) + log(mult)[b,k]) @ V
// FA2-style, mma.sync m16n8k8 tf32 (cvt.rna for unbiased rounding),
// Br=128 (8 warps x 16 rows), Bc=64, cp.async double-buffered K/V.

#define BATCH   2
#define HEADS   16
#define LQ      2048
#define LK      2048
#define DD      128
#define BR      128
#define BC      64
#define NTHREADS 256
#define PAD     132            // smem row stride in floats (conflict-free)
#define NT_S    8              // BC/8  (n-tiles for S = Q K^T)
#define KS_S    16             // DD/8  (k-steps for S)
#define NT_O    16             // DD/8  (n-tiles for O = P V)
#define KS_O    8              // BC/8  (k-steps for O)
#define NKT     (LK / BC)      // 32 key tiles

static constexpr int STAGE_FLOATS = 2 * BC * PAD;           // K tile + V tile (one stage)
static constexpr int SMEM_FLOATS  = 2 * STAGE_FLOATS + 2 * BC; // 2 stages + lm[2][64]
static constexpr int SMEM_BYTES   = SMEM_FLOATS * 4;        // 135,680 B

__device__ __forceinline__ uint32_t f2tf(float x) {
    uint32_t r;
    asm("cvt.rna.tf32.f32 %0, %1;" : "=r"(r) : "f"(x));
    return r;
}
__device__ __forceinline__ float ex2f(float x) {
    float r;
    asm("ex2.approx.ftz.f32 %0, %1;" : "=f"(r) : "f"(x));
    return r;
}
__device__ __forceinline__ void mma8(float c[4], const uint32_t a[4], uint32_t b0, uint32_t b1) {
    asm volatile(
        "mma.sync.aligned.m16n8k8.row.col.f32.tf32.tf32.f32 "
        "{%0,%1,%2,%3}, {%4,%5,%6,%7}, {%8,%9}, {%0,%1,%2,%3};"
        : "+f"(c[0]), "+f"(c[1]), "+f"(c[2]), "+f"(c[3])
        : "r"(a[0]), "r"(a[1]), "r"(a[2]), "r"(a[3]), "r"(b0), "r"(b1));
}
__device__ __forceinline__ void cp16(uint32_t dst, const void* src) {
    asm volatile("cp.async.cg.shared.global [%0], [%1], 16;" :: "r"(dst), "l"(src));
}

__global__ void __launch_bounds__(NTHREADS, 1)
softmax_set_attn_kernel(const float* __restrict__ Q, const float* __restrict__ K,
                        const float* __restrict__ V, const int* __restrict__ MULT,
                        float* __restrict__ O)
{
    extern __shared__ float smem[];
    float* lm_s = smem + 2 * STAGE_FLOATS;   // [2][64]

    const int tid  = threadIdx.x;
    const int w    = tid >> 5;
    const int lane = tid & 31;
    const int g    = lane >> 2;   // groupID 0..7
    const int tq   = lane & 3;    // thread-in-group 0..3
    const int bh   = blockIdx.y;
    const int qt   = blockIdx.x;
    const int b    = bh / HEADS;

    const float* Qp = Q + ((size_t)bh * LQ + (size_t)qt * BR) * DD;
    const float* Kp = K + (size_t)bh * LK * DD;
    const float* Vp = V + (size_t)bh * LK * DD;
    const int*   Mp = MULT + (size_t)b * LK;
    float*       Op = O + ((size_t)bh * LQ + (size_t)qt * BR) * DD;

    const uint32_t smem_base = (uint32_t)__cvta_generic_to_shared(smem);

    // ---- Stage Q through smem (coalesced), then load A-fragments (tf32) ----
    // Q tile 128x128 fits exactly in stage-0 region (128*132 = STAGE_FLOATS).
    #pragma unroll
    for (int i = 0; i < 16; i++) {
        int idx = tid + i * NTHREADS;      // float4 index, 0..4095
        int row = idx >> 5;
        int dc  = idx & 31;
        float4 v4 = *(const float4*)(Qp + (size_t)row * DD + dc * 4);
        *(float4*)(smem + row * PAD + dc * 4) = v4;
    }
    __syncthreads();

    uint32_t qa[KS_S][4];
    {
        const int r0 = w * 16 + g;
        const float* q0 = smem + r0 * PAD;
        const float* q1 = smem + (r0 + 8) * PAD;
        #pragma unroll
        for (int ks = 0; ks < KS_S; ks++) {
            qa[ks][0] = f2tf(q0[ks * 8 + tq]);
            qa[ks][1] = f2tf(q1[ks * 8 + tq]);
            qa[ks][2] = f2tf(q0[ks * 8 + tq + 4]);
            qa[ks][3] = f2tf(q1[ks * 8 + tq + 4]);
        }
    }
    __syncthreads();   // Q frags consumed from smem before cp.async overwrites

    // issue K/V tile kt into stage kt&1 (16B cp.async, fully coalesced)
    auto issue = [&](int kt) {
        int st = kt & 1;
        uint32_t kdst = smem_base + (uint32_t)(st * STAGE_FLOATS) * 4u;
        uint32_t vdst = kdst + (uint32_t)(BC * PAD) * 4u;
        const float* kg = Kp + (size_t)kt * BC * DD;
        const float* vg = Vp + (size_t)kt * BC * DD;
        #pragma unroll
        for (int i = 0; i < 8; i++) {
            int idx = tid + i * NTHREADS;  // 0..2047
            int row = idx >> 5;
            int dc  = idx & 31;
            uint32_t off = (uint32_t)(row * PAD + dc * 4) * 4u;
            cp16(kdst + off, kg + (size_t)row * DD + dc * 4);
            cp16(vdst + off, vg + (size_t)row * DD + dc * 4);
        }
    };

    float mv = 1.0f;
    if (tid < BC) mv = (float)Mp[tid];        // multiplicities for tile 0
    issue(0);
    asm volatile("cp.async.commit_group;");

    const float NEG_INF = __int_as_float(0xff800000);
    float m_r[2] = {NEG_INF, NEG_INF};
    float l_r[2] = {0.f, 0.f};
    float o[NT_O][4];
    #pragma unroll
    for (int n = 0; n < NT_O; n++) { o[n][0] = 0.f; o[n][1] = 0.f; o[n][2] = 0.f; o[n][3] = 0.f; }

    // base-2 softmax: s2 = s_raw * (log2e/sqrt(D)) + log2(mult)
    const float scale2 = 1.4426950408889634f / 11.313708498984760f;

    for (int kt = 0; kt < NKT; kt++) {
        const int st = kt & 1;

        // write log2(mult) for current tile (value loaded last iteration)
        if (tid < BC) lm_s[st * BC + tid] = __log2f(mv);

        if (kt + 1 < NKT) {
            issue(kt + 1);
            if (tid < BC) mv = (float)Mp[(kt + 1) * BC + tid];
        }
        asm volatile("cp.async.commit_group;");
        asm volatile("cp.async.wait_group 1;");
        __syncthreads();

        const float* Ks  = smem + st * STAGE_FLOATS;
        const float* Vs  = Ks + BC * PAD;
        const float* lmp = lm_s + st * BC;

        // ---- S = Q K^T (accumulate fp32) ----
        float sc[NT_S][4];
        #pragma unroll
        for (int n = 0; n < NT_S; n++) { sc[n][0]=0.f; sc[n][1]=0.f; sc[n][2]=0.f; sc[n][3]=0.f; }
        #pragma unroll
        for (int ks = 0; ks < KS_S; ks++) {
            #pragma unroll
            for (int n = 0; n < NT_S; n++) {
                const float* kr = Ks + (n * 8 + g) * PAD + ks * 8 + tq;
                uint32_t b0 = f2tf(kr[0]);
                uint32_t b1 = f2tf(kr[4]);
                mma8(sc[n], qa[ks], b0, b1);
            }
        }

        // ---- bias + online softmax ----
        float mx0 = NEG_INF, mx1 = NEG_INF;
        #pragma unroll
        for (int n = 0; n < NT_S; n++) {
            float lA = lmp[n * 8 + 2 * tq];
            float lB = lmp[n * 8 + 2 * tq + 1];
            sc[n][0] = fmaf(sc[n][0], scale2, lA);
            sc[n][1] = fmaf(sc[n][1], scale2, lB);
            sc[n][2] = fmaf(sc[n][2], scale2, lA);
            sc[n][3] = fmaf(sc[n][3], scale2, lB);
            mx0 = fmaxf(mx0, fmaxf(sc[n][0], sc[n][1]));
            mx1 = fmaxf(mx1, fmaxf(sc[n][2], sc[n][3]));
        }
        mx0 = fmaxf(mx0, __shfl_xor_sync(0xffffffffu, mx0, 1));
        mx0 = fmaxf(mx0, __shfl_xor_sync(0xffffffffu, mx0, 2));
        mx1 = fmaxf(mx1, __shfl_xor_sync(0xffffffffu, mx1, 1));
        mx1 = fmaxf(mx1, __shfl_xor_sync(0xffffffffu, mx1, 2));

        const float mn0 = fmaxf(m_r[0], mx0);
        const float mn1 = fmaxf(m_r[1], mx1);
        const float a0 = ex2f(m_r[0] - mn0);
        const float a1 = ex2f(m_r[1] - mn1);
        m_r[0] = mn0; m_r[1] = mn1;

        float ls0 = 0.f, ls1 = 0.f;
        uint32_t pa[NT_S][4];   // A-frags for PV: {c0,c2,c1,c3} ordering
        #pragma unroll
        for (int n = 0; n < NT_S; n++) {
            float p0 = ex2f(sc[n][0] - mn0);
            float p1 = ex2f(sc[n][1] - mn0);
            float p2 = ex2f(sc[n][2] - mn1);
            float p3 = ex2f(sc[n][3] - mn1);
            ls0 += p0 + p1;
            ls1 += p2 + p3;
            pa[n][0] = f2tf(p0);
            pa[n][1] = f2tf(p2);
            pa[n][2] = f2tf(p1);
            pa[n][3] = f2tf(p3);
        }
        l_r[0] = l_r[0] * a0 + ls0;
        l_r[1] = l_r[1] * a1 + ls1;
        #pragma unroll
        for (int n = 0; n < NT_O; n++) {
            o[n][0] *= a0; o[n][1] *= a0; o[n][2] *= a1; o[n][3] *= a1;
        }

        // ---- O += P V : key-permuted B-frags (b0<-key 2tq, b1<-key 2tq+1) ----
        #pragma unroll
        for (int ks = 0; ks < KS_O; ks++) {
            const float* vr0 = Vs + (ks * 8 + 2 * tq) * PAD + g;
            const float* vr1 = vr0 + PAD;
            #pragma unroll
            for (int n = 0; n < NT_O; n++) {
                uint32_t b0 = f2tf(vr0[n * 8]);
                uint32_t b1 = f2tf(vr1[n * 8]);
                mma8(o[n], pa[ks], b0, b1);
            }
        }
        __syncthreads();   // compute done before next issue overwrites this stage
    }

    // ---- epilogue: finish l reduction, normalize, store ----
    float lt0 = l_r[0];
    lt0 += __shfl_xor_sync(0xffffffffu, lt0, 1);
    lt0 += __shfl_xor_sync(0xffffffffu, lt0, 2);
    float lt1 = l_r[1];
    lt1 += __shfl_xor_sync(0xffffffffu, lt1, 1);
    lt1 += __shfl_xor_sync(0xffffffffu, lt1, 2);
    const float inv0 = __fdividef(1.f, lt0);
    const float inv1 = __fdividef(1.f, lt1);

    float* o0 = Op + (size_t)(w * 16 + g) * DD;
    float* o1 = Op + (size_t)(w * 16 + g + 8) * DD;
    #pragma unroll
    for (int n = 0; n < NT_O; n++) {
        int col = n * 8 + 2 * tq;
        float2 v0 = make_float2(o[n][0] * inv0, o[n][1] * inv0);
        float2 v1 = make_float2(o[n][2] * inv1, o[n][3] * inv1);
        *(float2*)(o0 + col) = v0;
        *(float2*)(o1 + col) = v1;
    }
}

extern "C" void kernel_launch(void* const* d_in, const int* in_sizes, int n_in,
                              void* d_out, int out_size)
{
    const float* Q = (const float*)d_in[0];
    const float* K = (const float*)d_in[1];
    const float* V = (const float*)d_in[2];
    const int*   M = (const int*)d_in[3];
    float*       O = (float*)d_out;

    cudaFuncSetAttribute(softmax_set_attn_kernel,
                         cudaFuncAttributeMaxDynamicSharedMemorySize, SMEM_BYTES);
    dim3 grid(LQ / BR, BATCH * HEADS);
    softmax_set_attn_kernel<<<grid, NTHREADS, SMEM_BYTES>>>(Q, K, V, M, O);
}